// round 8
// baseline (speedup 1.0000x reference)
#include <cuda_runtime.h>
#include <cstdint>

// TreePositionalEncodings — sm_100a, R8: L2-resident slice, lean registers.
//
// R7 proved evict_last residency cuts DRAM traffic (268->204MB/replay) but
// the 8-wide restructure blew registers (59) and occupancy (41.7%), slowing
// the SM-side store stream. R8 keeps the policy, fixes the shape:
//  - 8 consecutive features span <=2 dw groups -> (dw0,dw1,cross) scalars
//    instead of an 8-entry index array (2 LDS + 8 SEL per row).
//  - unroll 2 on the store loop so only one row of transients is live.
// Resident slice: batches 0-11 (100.7MB < 126MB L2) via
// st.global.L2::evict_last.v8.b32; rest streams evict-first.

#define D_MODEL   1024
#define MAX_LEN   2048
#define N_NODES   1364
#define BATCH     32
#define N_FEAT    51
#define N_DW      20
#define STRIP     32
#define STRIPS_PER_B (MAX_LEN / STRIP)   // 64
#define RESIDENT_BATCHES 12              // 100.7MB pinned in L2

__global__ void __launch_bounds__(256) tree_pos_enc_l2res2_kernel(
    const float* __restrict__ p,           // [64], first 51 used
    const float* __restrict__ positions,   // [BS, N_NODES, N_DW]; b=0 slice used
    float* __restrict__ out)               // [BS, MAX_LEN, D_MODEL]
{
    __shared__ float s_tp[N_FEAT];
    __shared__ float s_norm[N_FEAT];
    __shared__ float s_pos[STRIP][N_DW];

    const int bx   = blockIdx.x;            // 0..2047
    const int b    = bx >> 6;               // batch 0..31
    const int s0   = (bx & (STRIPS_PER_B - 1)) * STRIP;
    const int tid  = threadIdx.x;           // 0..255
    const int lane = tid & 127;             // owns 8 consecutive features
    const int rsel = tid >> 7;              // even/odd row within a pair

    if (tid < N_FEAT) {
        float tp = tanhf(p[tid]);
        s_tp[tid]   = tp;
        s_norm[tid] = sqrtf((1.0f - tp * tp) * (0.5f * (float)D_MODEL));
    }
    #pragma unroll
    for (int k = 0; k < (STRIP * N_DW + 255) / 256; k++) {
        int idx = tid + k * 256;
        if (idx < STRIP * N_DW) {
            int r = idx / N_DW, c = idx % N_DW;
            int s = s0 + r;
            float v = 0.0f;
            if (s >= 1 && s <= N_NODES)
                v = positions[(size_t)(s - 1) * N_DW + c];
            s_pos[r][c] = v;
        }
    }
    __syncthreads();

    // Per-thread invariants: 8 consecutive features j..j+7 cross at most ONE
    // dw-group boundary (N_FEAT=51 > 8). Keep (dw0, dw1, cross) scalars.
    const int j = lane * 8;                 // 0..1016
    const int dw0_raw = j / N_FEAT;         // 0..19
    int cross = (dw0_raw + 1) * N_FEAT - j; // elems still in dw0's group
    if (cross > 8) cross = 8;
    const int dw0 = dw0_raw;                           // always < N_DW here
    const int dw1 = (dw0_raw + 1 < N_DW) ? dw0_raw + 1 : dw0_raw;

    float w[8];
    #pragma unroll
    for (int e = 0; e < 8; e++) {
        int jj = j + e;
        int f  = jj % N_FEAT;
        int dw = jj / N_FEAT;               // 20 only for jj >= 1020 (pad)
        float ww = 0.0f;
        if (dw < N_DW) {
            float tp = s_tp[f];
            ww = s_norm[f];
            #pragma unroll 1
            for (int l = 0, lev = dw >> 2; l < lev; l++) ww *= tp;
        }
        w[e] = ww;
    }

    float* obase = out + (size_t)b * (MAX_LEN * D_MODEL)
                       + (size_t)s0 * D_MODEL + j;

    if (b < RESIDENT_BATCHES) {
        // L2-resident slice: 256-bit evict_last stores, low live-reg count.
        #pragma unroll 2
        for (int r = 0; r < STRIP; r += 2) {
            const int row = r + rsel;
            const float p0 = s_pos[row][dw0];
            const float p1 = s_pos[row][dw1];
            uint32_t v[8];
            #pragma unroll
            for (int e = 0; e < 8; e++) {
                float pv = (e < cross) ? p0 : p1;
                v[e] = __float_as_uint(w[e] * pv);
            }
            float* ptr = obase + (size_t)row * D_MODEL;
            asm volatile(
                "st.global.L2::evict_last.v8.b32 [%0], "
                "{%1, %2, %3, %4, %5, %6, %7, %8};"
                :: "l"(ptr),
                   "r"(v[0]), "r"(v[1]), "r"(v[2]), "r"(v[3]),
                   "r"(v[4]), "r"(v[5]), "r"(v[6]), "r"(v[7])
                : "memory");
        }
    } else {
        // Streaming slice: evict-first, doesn't displace the resident set.
        #pragma unroll 2
        for (int r = 0; r < STRIP; r += 2) {
            const int row = r + rsel;
            const float p0 = s_pos[row][dw0];
            const float p1 = s_pos[row][dw1];
            float rr[8];
            #pragma unroll
            for (int e = 0; e < 8; e++) {
                float pv = (e < cross) ? p0 : p1;
                rr[e] = w[e] * pv;
            }
            float4* ptr = reinterpret_cast<float4*>(obase + (size_t)row * D_MODEL);
            __stcs(ptr,     make_float4(rr[0], rr[1], rr[2], rr[3]));
            __stcs(ptr + 1, make_float4(rr[4], rr[5], rr[6], rr[7]));
        }
    }
}

extern "C" void kernel_launch(void* const* d_in, const int* in_sizes, int n_in,
                              void* d_out, int out_size) {
    const float* p         = (const float*)d_in[0];   // [64]
    const float* positions = (const float*)d_in[1];   // [32, 1364, 20]
    float* out             = (float*)d_out;           // [32, 2048, 1024]

    tree_pos_enc_l2res2_kernel<<<BATCH * STRIPS_PER_B, 256>>>(p, positions, out);
}

// round 9
// speedup vs baseline: 1.4072x; 1.4072x over previous
#include <cuda_runtime.h>

// TreePositionalEncodings — sm_100a, FINAL (R3 design).
//
// out[b, s, j]:
//   s == 0 or s > 1364  -> 0 ;  j >= 1020 -> 0
//   else                -> positions[0, s-1, j/51] * w[j]
// w[j] = tanh(p[j%51])^((j/51)/4) * sqrt((1-tanh^2)*1024/2)
//
// Roofline record (R1-R8): batch-scatter STG, contiguous-strip STG, TMA
// bulk store, STG+TMA hybrid, and L2::evict_last residency all converge on
// ~42.6us kernel / ~45us total — the DRAM write-stream ceiling for a 256MB
// full-buffer overwrite (~4.9TB/s to DRAM, ~6.3TB/s into L2, compute <10%).
// evict_last cut DRAM bytes but its L2-hit store path runs ~2x slower: net
// loss. This is the fastest verified configuration.
//
// Design: block = one contiguous 128KB strip (batch b x 32 rows). Weights
// (51 tanhf) rebuilt per-CTA, hidden under the store stream; per-thread
// loop-invariant w[4]; 32 sequential STG.128 rows, evict-first (.cs).

#define D_MODEL   1024
#define MAX_LEN   2048
#define N_NODES   1364
#define BATCH     32
#define N_FEAT    51
#define N_DW      20
#define STRIP     32
#define STRIPS_PER_B (MAX_LEN / STRIP)   // 64

__global__ void __launch_bounds__(256) tree_pos_enc_strip_kernel(
    const float* __restrict__ p,           // [64], first 51 used
    const float* __restrict__ positions,   // [BS, N_NODES, N_DW]; b=0 slice used
    float* __restrict__ out)               // [BS, MAX_LEN, D_MODEL]
{
    __shared__ float s_tp[N_FEAT];
    __shared__ float s_norm[N_FEAT];
    __shared__ float s_pos[STRIP][N_DW];

    const int bx  = blockIdx.x;            // 0..2047
    const int b   = bx >> 6;               // batch 0..31
    const int s0  = (bx & (STRIPS_PER_B - 1)) * STRIP;  // first row of strip
    const int tid = threadIdx.x;           // 0..255, each owns 4 features

    // Weight params (51 tanhf, hidden under the store stream).
    if (tid < N_FEAT) {
        float tp = tanhf(p[tid]);
        s_tp[tid]   = tp;
        s_norm[tid] = sqrtf((1.0f - tp * tp) * (0.5f * (float)D_MODEL));
    }
    // Position rows for this strip; inactive rows (s==0 or s>N_NODES) -> 0,
    // so the store loop stays uniform and emits zeros for them.
    #pragma unroll
    for (int k = 0; k < (STRIP * N_DW + 255) / 256; k++) {
        int idx = tid + k * 256;
        if (idx < STRIP * N_DW) {
            int r = idx / N_DW, c = idx % N_DW;
            int s = s0 + r;
            float v = 0.0f;
            if (s >= 1 && s <= N_NODES)
                v = positions[(size_t)(s - 1) * N_DW + c];
            s_pos[r][c] = v;
        }
    }
    __syncthreads();

    // Per-thread loop-invariant weights + dw indices (4 features each).
    const int j = tid * 4;
    float w[4];
    int   dwv[4];
    #pragma unroll
    for (int e = 0; e < 4; e++) {
        int jj = j + e;
        int f  = jj % N_FEAT;              // const divisor -> magic mul
        int dw = jj / N_FEAT;              // 20 only for jj >= 1020 (zero pad)
        dwv[e] = (dw < N_DW) ? dw : 0;
        float ww = 0.0f;
        if (dw < N_DW) {
            float tp = s_tp[f];
            ww = s_norm[f];
            #pragma unroll 1
            for (int l = 0, lev = dw >> 2; l < lev; l++) ww *= tp;
        }
        w[e] = ww;
    }

    // Stream 32 consecutive 4KB rows: fully sequential 128KB per block.
    float4* o = reinterpret_cast<float4*>(out)
              + (size_t)b * (MAX_LEN * (D_MODEL / 4))
              + (size_t)s0 * (D_MODEL / 4) + tid;
    #pragma unroll 8
    for (int r = 0; r < STRIP; r++) {
        float4 v;
        v.x = w[0] * s_pos[r][dwv[0]];
        v.y = w[1] * s_pos[r][dwv[1]];
        v.z = w[2] * s_pos[r][dwv[2]];
        v.w = w[3] * s_pos[r][dwv[3]];
        __stcs(o + (size_t)r * (D_MODEL / 4), v);
    }
}

extern "C" void kernel_launch(void* const* d_in, const int* in_sizes, int n_in,
                              void* d_out, int out_size) {
    const float* p         = (const float*)d_in[0];   // [64]
    const float* positions = (const float*)d_in[1];   // [32, 1364, 20]
    float* out             = (float*)d_out;           // [32, 2048, 1024]

    tree_pos_enc_strip_kernel<<<BATCH * STRIPS_PER_B, 256>>>(p, positions, out);
}